// round 9
// baseline (speedup 1.0000x reference)
#include <cuda_runtime.h>
#include <cstdint>
#include <cstddef>

// Problem constants
#define NB 4
#define NS 2048
#define NH 16
#define NDK 64
#define NDM 1024
#define NT (NB * NS)          // 8192 tokens
#define ATTN_SCALE 0.125f     // 1/sqrt(64)

// ---------------------------------------------------------------------------
// Scratch (device globals: no cudaMalloc allowed)
// ---------------------------------------------------------------------------
__device__ float g_q[(size_t)NB * NH * NS * NDK];        // 33.5 MB  [b][h][s][d]
__device__ float g_k[(size_t)NB * NH * NS * NDK];        // 33.5 MB
__device__ float g_v[(size_t)NB * NH * NS * NDK];        // 33.5 MB
__device__ float g_ctx[(size_t)NT * NDM];                // 33.5 MB  [b][s][h*64+d]

// ---------------------------------------------------------------------------
// Helpers
// ---------------------------------------------------------------------------
__device__ __forceinline__ unsigned f2tf_u(float f) {
    unsigned u;
    asm("cvt.rna.tf32.f32 %0, %1;" : "=r"(u) : "f"(f));
    return u;
}

__device__ __forceinline__ void mma_m16n8k8(float* c, const unsigned* a, const unsigned* b) {
    asm volatile(
        "mma.sync.aligned.m16n8k8.row.col.f32.tf32.tf32.f32 "
        "{%0,%1,%2,%3},{%4,%5,%6,%7},{%8,%9},{%0,%1,%2,%3};\n"
        : "+f"(c[0]), "+f"(c[1]), "+f"(c[2]), "+f"(c[3])
        : "r"(a[0]), "r"(a[1]), "r"(a[2]), "r"(a[3]), "r"(b[0]), "r"(b[1]));
}

__device__ __forceinline__ void cp_a16(float* smem_dst, const float* gsrc) {
    unsigned s = (unsigned)__cvta_generic_to_shared(smem_dst);
    asm volatile("cp.async.cg.shared.global [%0], [%1], 16;\n" :: "r"(s), "l"(gsrc));
}

// ---------------------------------------------------------------------------
// Double-buffered GEMM body: C[128,128] = A[128,Kd] * B[128,Kd]^T
// (both K-contiguous). 256 threads, 8 warps 2x4; warp tile 64x32; tf32 mma.
//
// tf32 conversion hoisted OUT of the inner fragment loop: after wait_group,
// each thread converts (in place, in SMEM) exactly the chunks it staged via
// its own cp.async ops (own-async results are thread-visible after own wait,
// so no extra barrier). Fragment loads are then plain LDS. Numerically
// IDENTICAL to cvt-at-fragment-load (cvt.rna applied once either way), but
// removes 24 cvt per warp per ks-step from the issue stream and shortens the
// LDS->HMMA dependency chain.
// ---------------------------------------------------------------------------
#define GEMM_SMEM_FLOATS (2 * 128 * 36 * 2)
#define GEMM_SMEM_BYTES  (GEMM_SMEM_FLOATS * 4)

__device__ __forceinline__ void gemm_tn_128x128_db(
    const float* __restrict__ A, const float* __restrict__ Bw, int Kd,
    float* sm, float acc[4][4][4])
{
    float* As = sm;                      // [2][128][36]
    float* Bs = sm + 2 * 128 * 36;       // [2][128][36]
    const int tid  = threadIdx.x;
    const int lane = tid & 31, warp = tid >> 5;
    const int g = lane >> 2, t = lane & 3;
    const int wm0 = (warp & 1) * 64, wn0 = (warp >> 1) * 32;

    const int nIter = Kd / 32;

    #pragma unroll
    for (int i = 0; i < 4; i++) {
        int s = tid + i * 256;
        int r = s >> 3, c4 = (s & 7) << 2;
        cp_a16(&As[(size_t)r * 36 + c4], A  + (size_t)r * Kd + c4);
        cp_a16(&Bs[(size_t)r * 36 + c4], Bw + (size_t)r * Kd + c4);
    }
    asm volatile("cp.async.commit_group;\n");

    for (int it = 0; it < nIter; it++) {
        const int cur = it & 1;
        if (it + 1 < nIter) {
            const int nxt = cur ^ 1;
            const int k0  = (it + 1) * 32;
            #pragma unroll
            for (int i = 0; i < 4; i++) {
                int s = tid + i * 256;
                int r = s >> 3, c4 = (s & 7) << 2;
                cp_a16(&As[((size_t)nxt * 128 + r) * 36 + c4], A  + (size_t)r * Kd + k0 + c4);
                cp_a16(&Bs[((size_t)nxt * 128 + r) * 36 + c4], Bw + (size_t)r * Kd + k0 + c4);
            }
            asm volatile("cp.async.commit_group;\n");
            asm volatile("cp.async.wait_group 1;\n");
        } else {
            asm volatile("cp.async.wait_group 0;\n");
        }

        float* Asb = As + (size_t)cur * 128 * 36;
        float* Bsb = Bs + (size_t)cur * 128 * 36;

        // in-place fp32 -> tf32 on the chunks THIS thread staged (own async
        // ops are visible after own wait_group; no barrier needed first).
        #pragma unroll
        for (int i = 0; i < 4; i++) {
            int s = tid + i * 256;
            int r = s >> 3, c4 = (s & 7) << 2;
            float4* pa = (float4*)&Asb[(size_t)r * 36 + c4];
            float4 va = *pa;
            *(uint4*)pa = make_uint4(f2tf_u(va.x), f2tf_u(va.y), f2tf_u(va.z), f2tf_u(va.w));
            float4* pb = (float4*)&Bsb[(size_t)r * 36 + c4];
            float4 vb = *pb;
            *(uint4*)pb = make_uint4(f2tf_u(vb.x), f2tf_u(vb.y), f2tf_u(vb.z), f2tf_u(vb.w));
        }
        __syncthreads();   // publish converted tiles

        #pragma unroll
        for (int ks = 0; ks < 32; ks += 8) {
            unsigned a[4][4], b[4][2];
            #pragma unroll
            for (int mi = 0; mi < 4; mi++) {
                int m = wm0 + mi * 16 + g;
                a[mi][0] = __float_as_uint(Asb[(size_t)(m    ) * 36 + ks + t    ]);
                a[mi][1] = __float_as_uint(Asb[(size_t)(m + 8) * 36 + ks + t    ]);
                a[mi][2] = __float_as_uint(Asb[(size_t)(m    ) * 36 + ks + t + 4]);
                a[mi][3] = __float_as_uint(Asb[(size_t)(m + 8) * 36 + ks + t + 4]);
            }
            #pragma unroll
            for (int ni = 0; ni < 4; ni++) {
                int n = wn0 + ni * 8 + g;
                b[ni][0] = __float_as_uint(Bsb[(size_t)n * 36 + ks + t    ]);
                b[ni][1] = __float_as_uint(Bsb[(size_t)n * 36 + ks + t + 4]);
            }
            #pragma unroll
            for (int mi = 0; mi < 4; mi++)
                #pragma unroll
                for (int ni = 0; ni < 4; ni++)
                    mma_m16n8k8(acc[mi][ni], a[mi], b[ni]);
        }
        __syncthreads();   // buffer `cur` safe for reuse at it+2
    }
}

// ---------------------------------------------------------------------------
// Kernel 1: fused QKV projection.
// ---------------------------------------------------------------------------
__global__ __launch_bounds__(256) void qkv_proj_kernel(
    const float* __restrict__ Qin, const float* __restrict__ Kin, const float* __restrict__ Vin,
    const float* __restrict__ Wq,  const float* __restrict__ Wk,  const float* __restrict__ Wv,
    const float* __restrict__ bq,  const float* __restrict__ bk,  const float* __restrict__ bv)
{
    extern __shared__ float smg[];
    const int z = blockIdx.z;
    const float* X    = (z == 0) ? Qin : (z == 1) ? Kin : Vin;
    const float* W    = (z == 0) ? Wq  : (z == 1) ? Wk  : Wv;
    const float* bias = (z == 0) ? bq  : (z == 1) ? bk  : bv;
    float* out        = (z == 0) ? g_q : (z == 1) ? g_k : g_v;

    float acc[4][4][4];
    #pragma unroll
    for (int i = 0; i < 4; i++)
        #pragma unroll
        for (int j = 0; j < 4; j++)
            #pragma unroll
            for (int k = 0; k < 4; k++) acc[i][j][k] = 0.f;

    gemm_tn_128x128_db(X + (size_t)blockIdx.y * 128 * NDM,
                       W + (size_t)blockIdx.x * 128 * NDM, NDM, smg, acc);

    const int tid = threadIdx.x, lane = tid & 31, warp = tid >> 5;
    const int g = lane >> 2, t = lane & 3;
    const int wm0 = (warp & 1) * 64, wn0 = (warp >> 1) * 32;
    const int row0 = blockIdx.y * 128, col0 = blockIdx.x * 128;

    #pragma unroll
    for (int mi = 0; mi < 4; mi++) {
        #pragma unroll
        for (int ni = 0; ni < 4; ni++) {
            int n = col0 + wn0 + ni * 8 + 2 * t;
            int h = n >> 6, d = n & 63;
            float b0v = bias[n], b1v = bias[n + 1];
            #pragma unroll
            for (int half = 0; half < 2; half++) {
                int m  = row0 + wm0 + mi * 16 + g + half * 8;
                int bb = m >> 11, s = m & 2047;
                size_t idx = (((size_t)(bb * NH + h) * NS) + s) * NDK + d;
                *(float2*)(out + idx) = make_float2(acc[mi][ni][half * 2 + 0] + b0v,
                                                    acc[mi][ni][half * 2 + 1] + b1v);
            }
        }
    }
}

// ---------------------------------------------------------------------------
// Kernel 2: fused flash attention, cp.async pipelined, P-in-registers.
// (unchanged from round 8 — kept diff-free for attribution)
//
// Permuted-K trick: K rows staged so that within each 8-key block, smem slot
// s holds key sigma(s), sigma = [0,4,1,5,2,6,3,7]. Then the S C-fragment
// {c0,c2,c1,c3} of slot-block ni IS the A-fragment (keys t, t+4) for the
// P@V mma over key-block ni -> P never goes through SMEM. V staged
// UNPERMUTED. relpos added per-KEY. Q fragments hoisted to regs at kt==0.
// ---------------------------------------------------------------------------
#define QS_STRIDE 68
#define KS_STRIDE 68
#define VS_STRIDE 72
#define ATTN_SMEM_FLOATS (128 * (QS_STRIDE + 2 * KS_STRIDE + VS_STRIDE))
#define ATTN_SMEM_BYTES  (ATTN_SMEM_FLOATS * 4)

__global__ __launch_bounds__(256, 1) void flash_attn_kernel(const float* __restrict__ relpos)
{
    extern __shared__ float sm[];
    float* Qs = sm;                                   // [128][68]
    float* Ks = Qs + 128 * QS_STRIDE;                 // [2][128][68] (rows permuted)
    float* Vs = Ks + 2 * 128 * KS_STRIDE;             // [128][72]   (rows natural)

    const int b = blockIdx.x, qt = blockIdx.y, h = blockIdx.z;
    const int bh = b * NH + h;
    const float* qp = g_q + (size_t)bh * NS * NDK + (size_t)qt * 128 * NDK;
    const float* kp = g_k + (size_t)bh * NS * NDK;
    const float* vp = g_v + (size_t)bh * NS * NDK;
    const float* rp = relpos + (size_t)h * NS * NS + (size_t)qt * 128 * NS;

    const int tid = threadIdx.x, lane = tid & 31, warp = tid >> 5;
    const int g = lane >> 2, t = lane & 3;
    const int wm = warp * 16;

    // prologue: Q -> Qs (natural) and K(0) -> Ks[0] (permuted rows), one group.
    #pragma unroll
    for (int i = 0; i < 8; i++) {
        int s = tid + i * 256;
        int r = s >> 4, c4 = (s & 15) << 2;
        cp_a16(&Qs[(size_t)r * QS_STRIDE + c4], qp + (size_t)r * NDK + c4);
        int c = r & 7;
        int ksrc_row = (r & ~7) | ((c >> 1) + ((c & 1) << 2));   // sigma
        cp_a16(&Ks[(size_t)r * KS_STRIDE + c4], kp + (size_t)ksrc_row * NDK + c4);
    }
    asm volatile("cp.async.commit_group;\n");

    float rm0 = -INFINITY, rm1 = -INFINITY;   // running max, rows (wm+g), (wm+g+8)
    float rs0 = 0.f, rs1 = 0.f;               // running sum
    float oacc[8][4];
    #pragma unroll
    for (int i = 0; i < 8; i++)
        #pragma unroll
        for (int j = 0; j < 4; j++) oacc[i][j] = 0.f;

    unsigned qreg[8][4];                      // Q fragments, loaded at kt==0

    for (int kt = 0; kt < NS / 128; kt++) {
        const int cur = kt & 1;

        // ---- group GV(kt): V(kt) -> Vs (natural rows) ----
        {
            const float* vsrc = vp + (size_t)kt * 128 * NDK;
            #pragma unroll
            for (int i = 0; i < 8; i++) {
                int s = tid + i * 256;
                int r = s >> 4, c4 = (s & 15) << 2;
                cp_a16(&Vs[(size_t)r * VS_STRIDE + c4], vsrc + (size_t)r * NDK + c4);
            }
            asm volatile("cp.async.commit_group;\n");
        }
        // ---- group GK(kt): K(kt+1) -> Ks[nxt] (permuted rows) ----
        if (kt + 1 < NS / 128) {
            const float* ksrc = kp + (size_t)(kt + 1) * 128 * NDK;
            float* kdst = Ks + (size_t)(cur ^ 1) * 128 * KS_STRIDE;
            #pragma unroll
            for (int i = 0; i < 8; i++) {
                int s = tid + i * 256;
                int r = s >> 4, c4 = (s & 15) << 2;
                int c = r & 7;
                int srow = (r & ~7) | ((c >> 1) + ((c & 1) << 2));
                cp_a16(&kdst[(size_t)r * KS_STRIDE + c4], ksrc + (size_t)srow * NDK + c4);
            }
            asm volatile("cp.async.commit_group;\n");
            asm volatile("cp.async.wait_group 2;\n");   // drain K(kt) [and Q]
        } else {
            asm volatile("cp.async.wait_group 1;\n");   // drain K(kt)
        }
        __syncthreads();

        if (kt == 0) {
            #pragma unroll
            for (int ks = 0; ks < 8; ks++) {
                qreg[ks][0] = f2tf_u(Qs[(size_t)(wm + g    ) * QS_STRIDE + ks * 8 + t    ]);
                qreg[ks][1] = f2tf_u(Qs[(size_t)(wm + g + 8) * QS_STRIDE + ks * 8 + t    ]);
                qreg[ks][2] = f2tf_u(Qs[(size_t)(wm + g    ) * QS_STRIDE + ks * 8 + t + 4]);
                qreg[ks][3] = f2tf_u(Qs[(size_t)(wm + g + 8) * QS_STRIDE + ks * 8 + t + 4]);
            }
        }

        const float* Ksb = Ks + (size_t)cur * 128 * KS_STRIDE;

        // ---- S = Q K^T : warp tile m16 x n128(slots), k=64 ----
        float sacc[16][4];
        #pragma unroll
        for (int i = 0; i < 16; i++)
            #pragma unroll
            for (int j = 0; j < 4; j++) sacc[i][j] = 0.f;

        #pragma unroll
        for (int ks = 0; ks < 8; ks++) {
            #pragma unroll
            for (int ni = 0; ni < 16; ni++) {
                unsigned bb[2];
                int n = ni * 8 + g;
                bb[0] = f2tf_u(Ksb[(size_t)n * KS_STRIDE + ks * 8 + t    ]);
                bb[1] = f2tf_u(Ksb[(size_t)n * KS_STRIDE + ks * 8 + t + 4]);
                mma_m16n8k8(sacc[ni], qreg[ks], bb);
            }
        }

        // ---- scale + relpos (per-KEY columns), tile row-max ----
        float m0 = -INFINITY, m1 = -INFINITY;
        const float* rp0 = rp + (size_t)(wm + g    ) * NS + kt * 128 + t;
        const float* rp1 = rp + (size_t)(wm + g + 8) * NS + kt * 128 + t;
        #pragma unroll
        for (int ni = 0; ni < 16; ni++) {
            sacc[ni][0] = sacc[ni][0] * ATTN_SCALE + rp0[ni * 8    ];
            sacc[ni][1] = sacc[ni][1] * ATTN_SCALE + rp0[ni * 8 + 4];
            sacc[ni][2] = sacc[ni][2] * ATTN_SCALE + rp1[ni * 8    ];
            sacc[ni][3] = sacc[ni][3] * ATTN_SCALE + rp1[ni * 8 + 4];
            m0 = fmaxf(m0, fmaxf(sacc[ni][0], sacc[ni][1]));
            m1 = fmaxf(m1, fmaxf(sacc[ni][2], sacc[ni][3]));
        }
        m0 = fmaxf(m0, __shfl_xor_sync(0xFFFFFFFFu, m0, 1));
        m0 = fmaxf(m0, __shfl_xor_sync(0xFFFFFFFFu, m0, 2));
        m1 = fmaxf(m1, __shfl_xor_sync(0xFFFFFFFFu, m1, 1));
        m1 = fmaxf(m1, __shfl_xor_sync(0xFFFFFFFFu, m1, 2));

        float nm0 = fmaxf(rm0, m0), nm1 = fmaxf(rm1, m1);
        float al0 = __expf(rm0 - nm0), al1 = __expf(rm1 - nm1);
        rm0 = nm0; rm1 = nm1;

        // ---- P = exp(S - m) in registers, row sums ----
        float ps0 = 0.f, ps1 = 0.f;
        #pragma unroll
        for (int ni = 0; ni < 16; ni++) {
            sacc[ni][0] = __expf(sacc[ni][0] - nm0);
            sacc[ni][1] = __expf(sacc[ni][1] - nm0);
            sacc[ni][2] = __expf(sacc[ni][2] - nm1);
            sacc[ni][3] = __expf(sacc[ni][3] - nm1);
            ps0 += sacc[ni][0] + sacc[ni][1];
            ps1 += sacc[ni][2] + sacc[ni][3];
        }
        ps0 += __shfl_xor_sync(0xFFFFFFFFu, ps0, 1);
        ps0 += __shfl_xor_sync(0xFFFFFFFFu, ps0, 2);
        ps1 += __shfl_xor_sync(0xFFFFFFFFu, ps1, 1);
        ps1 += __shfl_xor_sync(0xFFFFFFFFu, ps1, 2);
        rs0 = rs0 * al0 + ps0;
        rs1 = rs1 * al1 + ps1;

        // rescale O accumulator
        #pragma unroll
        for (int ni = 0; ni < 8; ni++) {
            oacc[ni][0] *= al0; oacc[ni][1] *= al0;
            oacc[ni][2] *= al1; oacc[ni][3] *= al1;
        }

        // ---- V(kt) visible; K(kt+1) may continue in flight ----
        if (kt + 1 < NS / 128) {
            asm volatile("cp.async.wait_group 1;\n");
        } else {
            asm volatile("cp.async.wait_group 0;\n");
        }
        __syncthreads();

        // ---- O += P V : P A-fragments straight from sacc (permuted match) ----
        #pragma unroll
        for (int ni = 0; ni < 16; ni++) {          // key-block = k-block
            unsigned aP[4];
            aP[0] = f2tf_u(sacc[ni][0]);   // (row g,   k=t)
            aP[1] = f2tf_u(sacc[ni][2]);   // (row g+8, k=t)
            aP[2] = f2tf_u(sacc[ni][1]);   // (row g,   k=t+4)
            aP[3] = f2tf_u(sacc[ni][3]);   // (row g+8, k=t+4)
            #pragma unroll
            for (int nj = 0; nj < 8; nj++) {
                unsigned bb[2];
                int n = nj * 8 + g;
                bb[0] = f2tf_u(Vs[(size_t)(ni * 8 + t    ) * VS_STRIDE + n]);
                bb[1] = f2tf_u(Vs[(size_t)(ni * 8 + t + 4) * VS_STRIDE + n]);
                mma_m16n8k8(oacc[nj], aP, bb);
            }
        }
        __syncthreads();   // all warps done with Vs / Ks[cur] before next-iter writes
    }

    // ---- epilogue: normalize, write ctx combined-head ----
    float inv0 = 1.f / rs0, inv1 = 1.f / rs1;
    #pragma unroll
    for (int ni = 0; ni < 8; ni++) {
        int d = ni * 8 + 2 * t;
        size_t i0 = ((size_t)b * NS + qt * 128 + wm + g    ) * NDM + h * 64 + d;
        size_t i1 = ((size_t)b * NS + qt * 128 + wm + g + 8) * NDM + h * 64 + d;
        *(float2*)(g_ctx + i0) = make_float2(oacc[ni][0] * inv0, oacc[ni][1] * inv0);
        *(float2*)(g_ctx + i1) = make_float2(oacc[ni][2] * inv1, oacc[ni][3] * inv1);
    }
}

// ---------------------------------------------------------------------------
// Kernel 3: out = ctx @ Wo^T + bo
// ---------------------------------------------------------------------------
__global__ __launch_bounds__(256) void out_proj_kernel(
    const float* __restrict__ Wo, const float* __restrict__ bo, float* __restrict__ out)
{
    extern __shared__ float smg[];
    float acc[4][4][4];
    #pragma unroll
    for (int i = 0; i < 4; i++)
        #pragma unroll
        for (int j = 0; j < 4; j++)
            #pragma unroll
            for (int k = 0; k < 4; k++) acc[i][j][k] = 0.f;

    gemm_tn_128x128_db(g_ctx + (size_t)blockIdx.y * 128 * NDM,
                       Wo    + (size_t)blockIdx.x * 128 * NDM, NDM, smg, acc);

    const int tid = threadIdx.x, lane = tid & 31, warp = tid >> 5;
    const int g = lane >> 2, t = lane & 3;
    const int wm0 = (warp & 1) * 64, wn0 = (warp >> 1) * 32;
    const int row0 = blockIdx.y * 128, col0 = blockIdx.x * 128;

    #pragma unroll
    for (int mi = 0; mi < 4; mi++) {
        #pragma unroll
        for (int ni = 0; ni < 4; ni++) {
            int n = col0 + wn0 + ni * 8 + 2 * t;
            float b0v = bo[n], b1v = bo[n + 1];
            #pragma unroll
            for (int half = 0; half < 2; half++) {
                int m = row0 + wm0 + mi * 16 + g + half * 8;
                *(float2*)(out + (size_t)m * NDM + n) =
                    make_float2(acc[mi][ni][half * 2 + 0] + b0v,
                                acc[mi][ni][half * 2 + 1] + b1v);
            }
        }
    }
}

// ---------------------------------------------------------------------------
// Launch
// ---------------------------------------------------------------------------
extern "C" void kernel_launch(void* const* d_in, const int* in_sizes, int n_in,
                              void* d_out, int out_size)
{
    (void)in_sizes; (void)n_in; (void)out_size;
    const float* Q      = (const float*)d_in[0];
    const float* K      = (const float*)d_in[1];
    const float* V      = (const float*)d_in[2];
    const float* Wq     = (const float*)d_in[3];
    const float* bq     = (const float*)d_in[4];
    const float* Wk     = (const float*)d_in[5];
    const float* bk     = (const float*)d_in[6];
    const float* Wv     = (const float*)d_in[7];
    const float* bv     = (const float*)d_in[8];
    const float* Wo     = (const float*)d_in[9];
    const float* bo     = (const float*)d_in[10];
    const float* relpos = (const float*)d_in[11];
    float* out = (float*)d_out;

    cudaFuncSetAttribute(flash_attn_kernel,
                         cudaFuncAttributeMaxDynamicSharedMemorySize, ATTN_SMEM_BYTES);
    cudaFuncSetAttribute(qkv_proj_kernel,
                         cudaFuncAttributeMaxDynamicSharedMemorySize, GEMM_SMEM_BYTES);
    cudaFuncSetAttribute(out_proj_kernel,
                         cudaFuncAttributeMaxDynamicSharedMemorySize, GEMM_SMEM_BYTES);

    dim3 blk(256);
    // 1) q,k,v = proj(Q/K/V) head-split
    qkv_proj_kernel<<<dim3(NDM / 128, NT / 128, 3), blk, GEMM_SMEM_BYTES>>>(
        Q, K, V, Wq, Wk, Wv, bq, bk, bv);
    // 2) fused attention (scores + relpos + softmax + ctx), batch-major grid for L2 relpos reuse
    flash_attn_kernel<<<dim3(NB, NS / 128, NH), blk, ATTN_SMEM_BYTES>>>(relpos);
    // 3) out = ctx @ Wo^T + bo
    out_proj_kernel<<<dim3(NDM / 128, NT / 128, 1), blk, GEMM_SMEM_BYTES>>>(Wo, bo, out);
}

// round 10
// speedup vs baseline: 1.0582x; 1.0582x over previous
#include <cuda_runtime.h>
#include <cstdint>
#include <cstddef>

// Problem constants
#define NB 4
#define NS 2048
#define NH 16
#define NDK 64
#define NDM 1024
#define NT (NB * NS)          // 8192 tokens
#define ATTN_SCALE 0.125f     // 1/sqrt(64)

// ---------------------------------------------------------------------------
// Scratch (device globals: no cudaMalloc allowed)
// ---------------------------------------------------------------------------
__device__ float g_q[(size_t)NB * NH * NS * NDK];        // 33.5 MB  [b][h][s][d]
__device__ float g_k[(size_t)NB * NH * NS * NDK];        // 33.5 MB
__device__ float g_v[(size_t)NB * NH * NS * NDK];        // 33.5 MB
__device__ float g_ctx[(size_t)NT * NDM];                // 33.5 MB  [b][s][h*64+d]

// ---------------------------------------------------------------------------
// Helpers
// ---------------------------------------------------------------------------
__device__ __forceinline__ unsigned f2tf_u(float f) {
    unsigned u;
    asm("cvt.rna.tf32.f32 %0, %1;" : "=r"(u) : "f"(f));
    return u;
}

__device__ __forceinline__ void mma_m16n8k8(float* c, const unsigned* a, const unsigned* b) {
    asm volatile(
        "mma.sync.aligned.m16n8k8.row.col.f32.tf32.tf32.f32 "
        "{%0,%1,%2,%3},{%4,%5,%6,%7},{%8,%9},{%0,%1,%2,%3};\n"
        : "+f"(c[0]), "+f"(c[1]), "+f"(c[2]), "+f"(c[3])
        : "r"(a[0]), "r"(a[1]), "r"(a[2]), "r"(a[3]), "r"(b[0]), "r"(b[1]));
}

__device__ __forceinline__ void cp_a16(float* smem_dst, const float* gsrc) {
    unsigned s = (unsigned)__cvta_generic_to_shared(smem_dst);
    asm volatile("cp.async.cg.shared.global [%0], [%1], 16;\n" :: "r"(s), "l"(gsrc));
}

// ---------------------------------------------------------------------------
// Double-buffered GEMM body: C[128,128] = A[128,Kd] * B[128,Kd]^T
// (both K-contiguous). 256 threads, 8 warps 2x4; warp tile 64x32; tf32 mma.
// REVERTED to the round-7 measured version (368us, tensor=46%): cvt.rna at
// fragment-load time. The round-9 staging-time in-place convert REGRESSED
// (L1 port 40->60%, issue 44->32%) — shared-crossbar traffic and the
// wait->barrier chain cost more than the ALU-pipe cvts saved.
// ---------------------------------------------------------------------------
#define GEMM_SMEM_FLOATS (2 * 128 * 36 * 2)
#define GEMM_SMEM_BYTES  (GEMM_SMEM_FLOATS * 4)

__device__ __forceinline__ void gemm_tn_128x128_db(
    const float* __restrict__ A, const float* __restrict__ Bw, int Kd,
    float* sm, float acc[4][4][4])
{
    float* As = sm;                      // [2][128][36]
    float* Bs = sm + 2 * 128 * 36;       // [2][128][36]
    const int tid  = threadIdx.x;
    const int lane = tid & 31, warp = tid >> 5;
    const int g = lane >> 2, t = lane & 3;
    const int wm0 = (warp & 1) * 64, wn0 = (warp >> 1) * 32;

    const int nIter = Kd / 32;

    #pragma unroll
    for (int i = 0; i < 4; i++) {
        int s = tid + i * 256;
        int r = s >> 3, c4 = (s & 7) << 2;
        cp_a16(&As[(size_t)r * 36 + c4], A  + (size_t)r * Kd + c4);
        cp_a16(&Bs[(size_t)r * 36 + c4], Bw + (size_t)r * Kd + c4);
    }
    asm volatile("cp.async.commit_group;\n");

    for (int it = 0; it < nIter; it++) {
        const int cur = it & 1;
        if (it + 1 < nIter) {
            const int nxt = cur ^ 1;
            const int k0  = (it + 1) * 32;
            #pragma unroll
            for (int i = 0; i < 4; i++) {
                int s = tid + i * 256;
                int r = s >> 3, c4 = (s & 7) << 2;
                cp_a16(&As[((size_t)nxt * 128 + r) * 36 + c4], A  + (size_t)r * Kd + k0 + c4);
                cp_a16(&Bs[((size_t)nxt * 128 + r) * 36 + c4], Bw + (size_t)r * Kd + k0 + c4);
            }
            asm volatile("cp.async.commit_group;\n");
            asm volatile("cp.async.wait_group 1;\n");
        } else {
            asm volatile("cp.async.wait_group 0;\n");
        }
        __syncthreads();

        const float* Asb = As + (size_t)cur * 128 * 36;
        const float* Bsb = Bs + (size_t)cur * 128 * 36;

        #pragma unroll
        for (int ks = 0; ks < 32; ks += 8) {
            unsigned a[4][4], b[4][2];
            #pragma unroll
            for (int mi = 0; mi < 4; mi++) {
                int m = wm0 + mi * 16 + g;
                a[mi][0] = f2tf_u(Asb[(size_t)(m    ) * 36 + ks + t    ]);
                a[mi][1] = f2tf_u(Asb[(size_t)(m + 8) * 36 + ks + t    ]);
                a[mi][2] = f2tf_u(Asb[(size_t)(m    ) * 36 + ks + t + 4]);
                a[mi][3] = f2tf_u(Asb[(size_t)(m + 8) * 36 + ks + t + 4]);
            }
            #pragma unroll
            for (int ni = 0; ni < 4; ni++) {
                int n = wn0 + ni * 8 + g;
                b[ni][0] = f2tf_u(Bsb[(size_t)n * 36 + ks + t    ]);
                b[ni][1] = f2tf_u(Bsb[(size_t)n * 36 + ks + t + 4]);
            }
            #pragma unroll
            for (int mi = 0; mi < 4; mi++)
                #pragma unroll
                for (int ni = 0; ni < 4; ni++)
                    mma_m16n8k8(acc[mi][ni], a[mi], b[ni]);
        }
        __syncthreads();
    }
}

// ---------------------------------------------------------------------------
// Kernel 1: fused QKV projection (round-7 measured configuration).
// ---------------------------------------------------------------------------
__global__ __launch_bounds__(256) void qkv_proj_kernel(
    const float* __restrict__ Qin, const float* __restrict__ Kin, const float* __restrict__ Vin,
    const float* __restrict__ Wq,  const float* __restrict__ Wk,  const float* __restrict__ Wv,
    const float* __restrict__ bq,  const float* __restrict__ bk,  const float* __restrict__ bv)
{
    extern __shared__ float smg[];
    const int z = blockIdx.z;
    const float* X    = (z == 0) ? Qin : (z == 1) ? Kin : Vin;
    const float* W    = (z == 0) ? Wq  : (z == 1) ? Wk  : Wv;
    const float* bias = (z == 0) ? bq  : (z == 1) ? bk  : bv;
    float* out        = (z == 0) ? g_q : (z == 1) ? g_k : g_v;

    float acc[4][4][4];
    #pragma unroll
    for (int i = 0; i < 4; i++)
        #pragma unroll
        for (int j = 0; j < 4; j++)
            #pragma unroll
            for (int k = 0; k < 4; k++) acc[i][j][k] = 0.f;

    gemm_tn_128x128_db(X + (size_t)blockIdx.y * 128 * NDM,
                       W + (size_t)blockIdx.x * 128 * NDM, NDM, smg, acc);

    const int tid = threadIdx.x, lane = tid & 31, warp = tid >> 5;
    const int g = lane >> 2, t = lane & 3;
    const int wm0 = (warp & 1) * 64, wn0 = (warp >> 1) * 32;
    const int row0 = blockIdx.y * 128, col0 = blockIdx.x * 128;

    #pragma unroll
    for (int mi = 0; mi < 4; mi++) {
        #pragma unroll
        for (int ni = 0; ni < 4; ni++) {
            int n = col0 + wn0 + ni * 8 + 2 * t;
            int h = n >> 6, d = n & 63;
            float b0v = bias[n], b1v = bias[n + 1];
            #pragma unroll
            for (int half = 0; half < 2; half++) {
                int m  = row0 + wm0 + mi * 16 + g + half * 8;
                int bb = m >> 11, s = m & 2047;
                size_t idx = (((size_t)(bb * NH + h) * NS) + s) * NDK + d;
                *(float2*)(out + idx) = make_float2(acc[mi][ni][half * 2 + 0] + b0v,
                                                    acc[mi][ni][half * 2 + 1] + b1v);
            }
        }
    }
}

// ---------------------------------------------------------------------------
// Kernel 2: fused flash attention, cp.async pipelined, P-in-registers.
// (byte-identical to rounds 8/9 — this bench isolates its effect:
//  flash ~= total - 368(qkv) - ~123(out_proj))
// ---------------------------------------------------------------------------
#define QS_STRIDE 68
#define KS_STRIDE 68
#define VS_STRIDE 72
#define ATTN_SMEM_FLOATS (128 * (QS_STRIDE + 2 * KS_STRIDE + VS_STRIDE))
#define ATTN_SMEM_BYTES  (ATTN_SMEM_FLOATS * 4)

__global__ __launch_bounds__(256, 1) void flash_attn_kernel(const float* __restrict__ relpos)
{
    extern __shared__ float sm[];
    float* Qs = sm;                                   // [128][68]
    float* Ks = Qs + 128 * QS_STRIDE;                 // [2][128][68] (rows permuted)
    float* Vs = Ks + 2 * 128 * KS_STRIDE;             // [128][72]   (rows natural)

    const int b = blockIdx.x, qt = blockIdx.y, h = blockIdx.z;
    const int bh = b * NH + h;
    const float* qp = g_q + (size_t)bh * NS * NDK + (size_t)qt * 128 * NDK;
    const float* kp = g_k + (size_t)bh * NS * NDK;
    const float* vp = g_v + (size_t)bh * NS * NDK;
    const float* rp = relpos + (size_t)h * NS * NS + (size_t)qt * 128 * NS;

    const int tid = threadIdx.x, lane = tid & 31, warp = tid >> 5;
    const int g = lane >> 2, t = lane & 3;
    const int wm = warp * 16;

    // prologue: Q -> Qs (natural) and K(0) -> Ks[0] (permuted rows), one group.
    #pragma unroll
    for (int i = 0; i < 8; i++) {
        int s = tid + i * 256;
        int r = s >> 4, c4 = (s & 15) << 2;
        cp_a16(&Qs[(size_t)r * QS_STRIDE + c4], qp + (size_t)r * NDK + c4);
        int c = r & 7;
        int ksrc_row = (r & ~7) | ((c >> 1) + ((c & 1) << 2));   // sigma
        cp_a16(&Ks[(size_t)r * KS_STRIDE + c4], kp + (size_t)ksrc_row * NDK + c4);
    }
    asm volatile("cp.async.commit_group;\n");

    float rm0 = -INFINITY, rm1 = -INFINITY;   // running max, rows (wm+g), (wm+g+8)
    float rs0 = 0.f, rs1 = 0.f;               // running sum
    float oacc[8][4];
    #pragma unroll
    for (int i = 0; i < 8; i++)
        #pragma unroll
        for (int j = 0; j < 4; j++) oacc[i][j] = 0.f;

    unsigned qreg[8][4];                      // Q fragments, loaded at kt==0

    for (int kt = 0; kt < NS / 128; kt++) {
        const int cur = kt & 1;

        // ---- group GV(kt): V(kt) -> Vs (natural rows) ----
        {
            const float* vsrc = vp + (size_t)kt * 128 * NDK;
            #pragma unroll
            for (int i = 0; i < 8; i++) {
                int s = tid + i * 256;
                int r = s >> 4, c4 = (s & 15) << 2;
                cp_a16(&Vs[(size_t)r * VS_STRIDE + c4], vsrc + (size_t)r * NDK + c4);
            }
            asm volatile("cp.async.commit_group;\n");
        }
        // ---- group GK(kt): K(kt+1) -> Ks[nxt] (permuted rows) ----
        if (kt + 1 < NS / 128) {
            const float* ksrc = kp + (size_t)(kt + 1) * 128 * NDK;
            float* kdst = Ks + (size_t)(cur ^ 1) * 128 * KS_STRIDE;
            #pragma unroll
            for (int i = 0; i < 8; i++) {
                int s = tid + i * 256;
                int r = s >> 4, c4 = (s & 15) << 2;
                int c = r & 7;
                int srow = (r & ~7) | ((c >> 1) + ((c & 1) << 2));
                cp_a16(&kdst[(size_t)r * KS_STRIDE + c4], ksrc + (size_t)srow * NDK + c4);
            }
            asm volatile("cp.async.commit_group;\n");
            asm volatile("cp.async.wait_group 2;\n");   // drain K(kt) [and Q]
        } else {
            asm volatile("cp.async.wait_group 1;\n");   // drain K(kt)
        }
        __syncthreads();

        if (kt == 0) {
            #pragma unroll
            for (int ks = 0; ks < 8; ks++) {
                qreg[ks][0] = f2tf_u(Qs[(size_t)(wm + g    ) * QS_STRIDE + ks * 8 + t    ]);
                qreg[ks][1] = f2tf_u(Qs[(size_t)(wm + g + 8) * QS_STRIDE + ks * 8 + t    ]);
                qreg[ks][2] = f2tf_u(Qs[(size_t)(wm + g    ) * QS_STRIDE + ks * 8 + t + 4]);
                qreg[ks][3] = f2tf_u(Qs[(size_t)(wm + g + 8) * QS_STRIDE + ks * 8 + t + 4]);
            }
        }

        const float* Ksb = Ks + (size_t)cur * 128 * KS_STRIDE;

        // ---- S = Q K^T : warp tile m16 x n128(slots), k=64 ----
        float sacc[16][4];
        #pragma unroll
        for (int i = 0; i < 16; i++)
            #pragma unroll
            for (int j = 0; j < 4; j++) sacc[i][j] = 0.f;

        #pragma unroll
        for (int ks = 0; ks < 8; ks++) {
            #pragma unroll
            for (int ni = 0; ni < 16; ni++) {
                unsigned bb[2];
                int n = ni * 8 + g;
                bb[0] = f2tf_u(Ksb[(size_t)n * KS_STRIDE + ks * 8 + t    ]);
                bb[1] = f2tf_u(Ksb[(size_t)n * KS_STRIDE + ks * 8 + t + 4]);
                mma_m16n8k8(sacc[ni], qreg[ks], bb);
            }
        }

        // ---- scale + relpos (per-KEY columns), tile row-max ----
        float m0 = -INFINITY, m1 = -INFINITY;
        const float* rp0 = rp + (size_t)(wm + g    ) * NS + kt * 128 + t;
        const float* rp1 = rp + (size_t)(wm + g + 8) * NS + kt * 128 + t;
        #pragma unroll
        for (int ni = 0; ni < 16; ni++) {
            sacc[ni][0] = sacc[ni][0] * ATTN_SCALE + rp0[ni * 8    ];
            sacc[ni][1] = sacc[ni][1] * ATTN_SCALE + rp0[ni * 8 + 4];
            sacc[ni][2] = sacc[ni][2] * ATTN_SCALE + rp1[ni * 8    ];
            sacc[ni][3] = sacc[ni][3] * ATTN_SCALE + rp1[ni * 8 + 4];
            m0 = fmaxf(m0, fmaxf(sacc[ni][0], sacc[ni][1]));
            m1 = fmaxf(m1, fmaxf(sacc[ni][2], sacc[ni][3]));
        }
        m0 = fmaxf(m0, __shfl_xor_sync(0xFFFFFFFFu, m0, 1));
        m0 = fmaxf(m0, __shfl_xor_sync(0xFFFFFFFFu, m0, 2));
        m1 = fmaxf(m1, __shfl_xor_sync(0xFFFFFFFFu, m1, 1));
        m1 = fmaxf(m1, __shfl_xor_sync(0xFFFFFFFFu, m1, 2));

        float nm0 = fmaxf(rm0, m0), nm1 = fmaxf(rm1, m1);
        float al0 = __expf(rm0 - nm0), al1 = __expf(rm1 - nm1);
        rm0 = nm0; rm1 = nm1;

        // ---- P = exp(S - m) in registers, row sums ----
        float ps0 = 0.f, ps1 = 0.f;
        #pragma unroll
        for (int ni = 0; ni < 16; ni++) {
            sacc[ni][0] = __expf(sacc[ni][0] - nm0);
            sacc[ni][1] = __expf(sacc[ni][1] - nm0);
            sacc[ni][2] = __expf(sacc[ni][2] - nm1);
            sacc[ni][3] = __expf(sacc[ni][3] - nm1);
            ps0 += sacc[ni][0] + sacc[ni][1];
            ps1 += sacc[ni][2] + sacc[ni][3];
        }
        ps0 += __shfl_xor_sync(0xFFFFFFFFu, ps0, 1);
        ps0 += __shfl_xor_sync(0xFFFFFFFFu, ps0, 2);
        ps1 += __shfl_xor_sync(0xFFFFFFFFu, ps1, 1);
        ps1 += __shfl_xor_sync(0xFFFFFFFFu, ps1, 2);
        rs0 = rs0 * al0 + ps0;
        rs1 = rs1 * al1 + ps1;

        // rescale O accumulator
        #pragma unroll
        for (int ni = 0; ni < 8; ni++) {
            oacc[ni][0] *= al0; oacc[ni][1] *= al0;
            oacc[ni][2] *= al1; oacc[ni][3] *= al1;
        }

        // ---- V(kt) visible; K(kt+1) may continue in flight ----
        if (kt + 1 < NS / 128) {
            asm volatile("cp.async.wait_group 1;\n");
        } else {
            asm volatile("cp.async.wait_group 0;\n");
        }
        __syncthreads();

        // ---- O += P V : P A-fragments straight from sacc (permuted match) ----
        #pragma unroll
        for (int ni = 0; ni < 16; ni++) {          // key-block = k-block
            unsigned aP[4];
            aP[0] = f2tf_u(sacc[ni][0]);   // (row g,   k=t)
            aP[1] = f2tf_u(sacc[ni][2]);   // (row g+8, k=t)
            aP[2] = f2tf_u(sacc[ni][1]);   // (row g,   k=t+4)
            aP[3] = f2tf_u(sacc[ni][3]);   // (row g+8, k=t+4)
            #pragma unroll
            for (int nj = 0; nj < 8; nj++) {
                unsigned bb[2];
                int n = nj * 8 + g;
                bb[0] = f2tf_u(Vs[(size_t)(ni * 8 + t    ) * VS_STRIDE + n]);
                bb[1] = f2tf_u(Vs[(size_t)(ni * 8 + t + 4) * VS_STRIDE + n]);
                mma_m16n8k8(oacc[nj], aP, bb);
            }
        }
        __syncthreads();   // all warps done with Vs / Ks[cur] before next-iter writes
    }

    // ---- epilogue: normalize, write ctx combined-head ----
    float inv0 = 1.f / rs0, inv1 = 1.f / rs1;
    #pragma unroll
    for (int ni = 0; ni < 8; ni++) {
        int d = ni * 8 + 2 * t;
        size_t i0 = ((size_t)b * NS + qt * 128 + wm + g    ) * NDM + h * 64 + d;
        size_t i1 = ((size_t)b * NS + qt * 128 + wm + g + 8) * NDM + h * 64 + d;
        *(float2*)(g_ctx + i0) = make_float2(oacc[ni][0] * inv0, oacc[ni][1] * inv0);
        *(float2*)(g_ctx + i1) = make_float2(oacc[ni][2] * inv1, oacc[ni][3] * inv1);
    }
}

// ---------------------------------------------------------------------------
// Kernel 3: out = ctx @ Wo^T + bo (round-7 measured configuration).
// ---------------------------------------------------------------------------
__global__ __launch_bounds__(256) void out_proj_kernel(
    const float* __restrict__ Wo, const float* __restrict__ bo, float* __restrict__ out)
{
    extern __shared__ float smg[];
    float acc[4][4][4];
    #pragma unroll
    for (int i = 0; i < 4; i++)
        #pragma unroll
        for (int j = 0; j < 4; j++)
            #pragma unroll
            for (int k = 0; k < 4; k++) acc[i][j][k] = 0.f;

    gemm_tn_128x128_db(g_ctx + (size_t)blockIdx.y * 128 * NDM,
                       Wo    + (size_t)blockIdx.x * 128 * NDM, NDM, smg, acc);

    const int tid = threadIdx.x, lane = tid & 31, warp = tid >> 5;
    const int g = lane >> 2, t = lane & 3;
    const int wm0 = (warp & 1) * 64, wn0 = (warp >> 1) * 32;
    const int row0 = blockIdx.y * 128, col0 = blockIdx.x * 128;

    #pragma unroll
    for (int mi = 0; mi < 4; mi++) {
        #pragma unroll
        for (int ni = 0; ni < 4; ni++) {
            int n = col0 + wn0 + ni * 8 + 2 * t;
            float b0v = bo[n], b1v = bo[n + 1];
            #pragma unroll
            for (int half = 0; half < 2; half++) {
                int m = row0 + wm0 + mi * 16 + g + half * 8;
                *(float2*)(out + (size_t)m * NDM + n) =
                    make_float2(acc[mi][ni][half * 2 + 0] + b0v,
                                acc[mi][ni][half * 2 + 1] + b1v);
            }
        }
    }
}

// ---------------------------------------------------------------------------
// Launch
// ---------------------------------------------------------------------------
extern "C" void kernel_launch(void* const* d_in, const int* in_sizes, int n_in,
                              void* d_out, int out_size)
{
    (void)in_sizes; (void)n_in; (void)out_size;
    const float* Q      = (const float*)d_in[0];
    const float* K      = (const float*)d_in[1];
    const float* V      = (const float*)d_in[2];
    const float* Wq     = (const float*)d_in[3];
    const float* bq     = (const float*)d_in[4];
    const float* Wk     = (const float*)d_in[5];
    const float* bk     = (const float*)d_in[6];
    const float* Wv     = (const float*)d_in[7];
    const float* bv     = (const float*)d_in[8];
    const float* Wo     = (const float*)d_in[9];
    const float* bo     = (const float*)d_in[10];
    const float* relpos = (const float*)d_in[11];
    float* out = (float*)d_out;

    cudaFuncSetAttribute(flash_attn_kernel,
                         cudaFuncAttributeMaxDynamicSharedMemorySize, ATTN_SMEM_BYTES);
    cudaFuncSetAttribute(qkv_proj_kernel,
                         cudaFuncAttributeMaxDynamicSharedMemorySize, GEMM_SMEM_BYTES);
    cudaFuncSetAttribute(out_proj_kernel,
                         cudaFuncAttributeMaxDynamicSharedMemorySize, GEMM_SMEM_BYTES);

    dim3 blk(256);
    // 1) q,k,v = proj(Q/K/V) head-split
    qkv_proj_kernel<<<dim3(NDM / 128, NT / 128, 3), blk, GEMM_SMEM_BYTES>>>(
        Q, K, V, Wq, Wk, Wv, bq, bk, bv);
    // 2) fused attention (scores + relpos + softmax + ctx), batch-major grid for L2 relpos reuse
    flash_attn_kernel<<<dim3(NB, NS / 128, NH), blk, ATTN_SMEM_BYTES>>>(relpos);
    // 3) out = ctx @ Wo^T + bo
    out_proj_kernel<<<dim3(NDM / 128, NT / 128, 1), blk, GEMM_SMEM_BYTES>>>(Wo, bo, out);
}

// round 12
// speedup vs baseline: 1.1399x; 1.0772x over previous
#include <cuda_runtime.h>
#include <cstdint>
#include <cstddef>

// Problem constants
#define NB 4
#define NS 2048
#define NH 16
#define NDK 64
#define NDM 1024
#define NT (NB * NS)          // 8192 tokens
#define ATTN_SCALE 0.125f     // 1/sqrt(64)

// ---------------------------------------------------------------------------
// Scratch (device globals: no cudaMalloc allowed)
// g_q/g_k/g_v hold TF32-PREROUNDED values (cvt.rna applied at qkv epilogue).
// cvt.rna is idempotent, so flash consuming them raw is bit-identical to
// cvt-at-load.
// ---------------------------------------------------------------------------
__device__ float g_q[(size_t)NB * NH * NS * NDK];        // 33.5 MB  [b][h][s][d]
__device__ float g_k[(size_t)NB * NH * NS * NDK];        // 33.5 MB
__device__ float g_v[(size_t)NB * NH * NS * NDK];        // 33.5 MB
__device__ float g_ctx[(size_t)NT * NDM];                // 33.5 MB  [b][s][h*64+d]

// ---------------------------------------------------------------------------
// Helpers
// ---------------------------------------------------------------------------
__device__ __forceinline__ unsigned f2tf_u(float f) {
    unsigned u;
    asm("cvt.rna.tf32.f32 %0, %1;" : "=r"(u) : "f"(f));
    return u;
}

__device__ __forceinline__ float f2tf(float f) {
    return __uint_as_float(f2tf_u(f));
}

__device__ __forceinline__ void mma_m16n8k8(float* c, const unsigned* a, const unsigned* b) {
    asm volatile(
        "mma.sync.aligned.m16n8k8.row.col.f32.tf32.tf32.f32 "
        "{%0,%1,%2,%3},{%4,%5,%6,%7},{%8,%9},{%0,%1,%2,%3};\n"
        : "+f"(c[0]), "+f"(c[1]), "+f"(c[2]), "+f"(c[3])
        : "r"(a[0]), "r"(a[1]), "r"(a[2]), "r"(a[3]), "r"(b[0]), "r"(b[1]));
}

__device__ __forceinline__ void cp_a16(float* smem_dst, const float* gsrc) {
    unsigned s = (unsigned)__cvta_generic_to_shared(smem_dst);
    asm volatile("cp.async.cg.shared.global [%0], [%1], 16;\n" :: "r"(s), "l"(gsrc));
}

// ---------------------------------------------------------------------------
// Double-buffered GEMM body (round-7 measured config: 368us, tensor=46%).
// cvt.rna at fragment-load time (round-9 staging-convert regressed; reverted).
// ---------------------------------------------------------------------------
#define GEMM_SMEM_FLOATS (2 * 128 * 36 * 2)
#define GEMM_SMEM_BYTES  (GEMM_SMEM_FLOATS * 4)

__device__ __forceinline__ void gemm_tn_128x128_db(
    const float* __restrict__ A, const float* __restrict__ Bw, int Kd,
    float* sm, float acc[4][4][4])
{
    float* As = sm;                      // [2][128][36]
    float* Bs = sm + 2 * 128 * 36;       // [2][128][36]
    const int tid  = threadIdx.x;
    const int lane = tid & 31, warp = tid >> 5;
    const int g = lane >> 2, t = lane & 3;
    const int wm0 = (warp & 1) * 64, wn0 = (warp >> 1) * 32;

    const int nIter = Kd / 32;

    #pragma unroll
    for (int i = 0; i < 4; i++) {
        int s = tid + i * 256;
        int r = s >> 3, c4 = (s & 7) << 2;
        cp_a16(&As[(size_t)r * 36 + c4], A  + (size_t)r * Kd + c4);
        cp_a16(&Bs[(size_t)r * 36 + c4], Bw + (size_t)r * Kd + c4);
    }
    asm volatile("cp.async.commit_group;\n");

    for (int it = 0; it < nIter; it++) {
        const int cur = it & 1;
        if (it + 1 < nIter) {
            const int nxt = cur ^ 1;
            const int k0  = (it + 1) * 32;
            #pragma unroll
            for (int i = 0; i < 4; i++) {
                int s = tid + i * 256;
                int r = s >> 3, c4 = (s & 7) << 2;
                cp_a16(&As[((size_t)nxt * 128 + r) * 36 + c4], A  + (size_t)r * Kd + k0 + c4);
                cp_a16(&Bs[((size_t)nxt * 128 + r) * 36 + c4], Bw + (size_t)r * Kd + k0 + c4);
            }
            asm volatile("cp.async.commit_group;\n");
            asm volatile("cp.async.wait_group 1;\n");
        } else {
            asm volatile("cp.async.wait_group 0;\n");
        }
        __syncthreads();

        const float* Asb = As + (size_t)cur * 128 * 36;
        const float* Bsb = Bs + (size_t)cur * 128 * 36;

        #pragma unroll
        for (int ks = 0; ks < 32; ks += 8) {
            unsigned a[4][4], b[4][2];
            #pragma unroll
            for (int mi = 0; mi < 4; mi++) {
                int m = wm0 + mi * 16 + g;
                a[mi][0] = f2tf_u(Asb[(size_t)(m    ) * 36 + ks + t    ]);
                a[mi][1] = f2tf_u(Asb[(size_t)(m + 8) * 36 + ks + t    ]);
                a[mi][2] = f2tf_u(Asb[(size_t)(m    ) * 36 + ks + t + 4]);
                a[mi][3] = f2tf_u(Asb[(size_t)(m + 8) * 36 + ks + t + 4]);
            }
            #pragma unroll
            for (int ni = 0; ni < 4; ni++) {
                int n = wn0 + ni * 8 + g;
                b[ni][0] = f2tf_u(Bsb[(size_t)n * 36 + ks + t    ]);
                b[ni][1] = f2tf_u(Bsb[(size_t)n * 36 + ks + t + 4]);
            }
            #pragma unroll
            for (int mi = 0; mi < 4; mi++)
                #pragma unroll
                for (int ni = 0; ni < 4; ni++)
                    mma_m16n8k8(acc[mi][ni], a[mi], b[ni]);
        }
        __syncthreads();
    }
}

// ---------------------------------------------------------------------------
// Kernel 1: fused QKV projection. Epilogue stores TF32-PREROUNDED values
// (bit-identical downstream; kills 512 cvt/warp/iter in flash).
// ---------------------------------------------------------------------------
__global__ __launch_bounds__(256) void qkv_proj_kernel(
    const float* __restrict__ Qin, const float* __restrict__ Kin, const float* __restrict__ Vin,
    const float* __restrict__ Wq,  const float* __restrict__ Wk,  const float* __restrict__ Wv,
    const float* __restrict__ bq,  const float* __restrict__ bk,  const float* __restrict__ bv)
{
    extern __shared__ float smg[];
    const int z = blockIdx.z;
    const float* X    = (z == 0) ? Qin : (z == 1) ? Kin : Vin;
    const float* W    = (z == 0) ? Wq  : (z == 1) ? Wk  : Wv;
    const float* bias = (z == 0) ? bq  : (z == 1) ? bk  : bv;
    float* out        = (z == 0) ? g_q : (z == 1) ? g_k : g_v;

    float acc[4][4][4];
    #pragma unroll
    for (int i = 0; i < 4; i++)
        #pragma unroll
        for (int j = 0; j < 4; j++)
            #pragma unroll
            for (int k = 0; k < 4; k++) acc[i][j][k] = 0.f;

    gemm_tn_128x128_db(X + (size_t)blockIdx.y * 128 * NDM,
                       W + (size_t)blockIdx.x * 128 * NDM, NDM, smg, acc);

    const int tid = threadIdx.x, lane = tid & 31, warp = tid >> 5;
    const int g = lane >> 2, t = lane & 3;
    const int wm0 = (warp & 1) * 64, wn0 = (warp >> 1) * 32;
    const int row0 = blockIdx.y * 128, col0 = blockIdx.x * 128;

    #pragma unroll
    for (int mi = 0; mi < 4; mi++) {
        #pragma unroll
        for (int ni = 0; ni < 4; ni++) {
            int n = col0 + wn0 + ni * 8 + 2 * t;
            int h = n >> 6, d = n & 63;
            float b0v = bias[n], b1v = bias[n + 1];
            #pragma unroll
            for (int half = 0; half < 2; half++) {
                int m  = row0 + wm0 + mi * 16 + g + half * 8;
                int bb = m >> 11, s = m & 2047;
                size_t idx = (((size_t)(bb * NH + h) * NS) + s) * NDK + d;
                *(float2*)(out + idx) = make_float2(f2tf(acc[mi][ni][half * 2 + 0] + b0v),
                                                    f2tf(acc[mi][ni][half * 2 + 1] + b1v));
            }
        }
    }
}

// ---------------------------------------------------------------------------
// Kernel 2: fused flash attention, cp.async pipelined, P-in-registers.
// Q/K/V arrive TF32-prerounded from g_q/g_k/g_v -> fragment loads are plain
// LDS (no cvt). Only P (computed fresh) still needs cvt before P@V.
// Structure otherwise identical to rounds 8-10 (permuted-K sigma trick).
// ---------------------------------------------------------------------------
#define QS_STRIDE 68
#define KS_STRIDE 68
#define VS_STRIDE 72
#define ATTN_SMEM_FLOATS (128 * (QS_STRIDE + 2 * KS_STRIDE + VS_STRIDE))
#define ATTN_SMEM_BYTES  (ATTN_SMEM_FLOATS * 4)

__global__ __launch_bounds__(256, 1) void flash_attn_kernel(const float* __restrict__ relpos)
{
    extern __shared__ float sm[];
    float* Qs = sm;                                   // [128][68]
    float* Ks = Qs + 128 * QS_STRIDE;                 // [2][128][68] (rows permuted)
    float* Vs = Ks + 2 * 128 * KS_STRIDE;             // [128][72]   (rows natural)

    const int b = blockIdx.x, qt = blockIdx.y, h = blockIdx.z;
    const int bh = b * NH + h;
    const float* qp = g_q + (size_t)bh * NS * NDK + (size_t)qt * 128 * NDK;
    const float* kp = g_k + (size_t)bh * NS * NDK;
    const float* vp = g_v + (size_t)bh * NS * NDK;
    const float* rp = relpos + (size_t)h * NS * NS + (size_t)qt * 128 * NS;

    const int tid = threadIdx.x, lane = tid & 31, warp = tid >> 5;
    const int g = lane >> 2, t = lane & 3;
    const int wm = warp * 16;

    // prologue: Q -> Qs (natural) and K(0) -> Ks[0] (permuted rows), one group.
    #pragma unroll
    for (int i = 0; i < 8; i++) {
        int s = tid + i * 256;
        int r = s >> 4, c4 = (s & 15) << 2;
        cp_a16(&Qs[(size_t)r * QS_STRIDE + c4], qp + (size_t)r * NDK + c4);
        int c = r & 7;
        int ksrc_row = (r & ~7) | ((c >> 1) + ((c & 1) << 2));   // sigma
        cp_a16(&Ks[(size_t)r * KS_STRIDE + c4], kp + (size_t)ksrc_row * NDK + c4);
    }
    asm volatile("cp.async.commit_group;\n");

    float rm0 = -INFINITY, rm1 = -INFINITY;   // running max, rows (wm+g), (wm+g+8)
    float rs0 = 0.f, rs1 = 0.f;               // running sum
    float oacc[8][4];
    #pragma unroll
    for (int i = 0; i < 8; i++)
        #pragma unroll
        for (int j = 0; j < 4; j++) oacc[i][j] = 0.f;

    unsigned qreg[8][4];                      // Q fragments, loaded at kt==0

    for (int kt = 0; kt < NS / 128; kt++) {
        const int cur = kt & 1;

        // ---- group GV(kt): V(kt) -> Vs (natural rows) ----
        {
            const float* vsrc = vp + (size_t)kt * 128 * NDK;
            #pragma unroll
            for (int i = 0; i < 8; i++) {
                int s = tid + i * 256;
                int r = s >> 4, c4 = (s & 15) << 2;
                cp_a16(&Vs[(size_t)r * VS_STRIDE + c4], vsrc + (size_t)r * NDK + c4);
            }
            asm volatile("cp.async.commit_group;\n");
        }
        // ---- group GK(kt): K(kt+1) -> Ks[nxt] (permuted rows) ----
        if (kt + 1 < NS / 128) {
            const float* ksrc = kp + (size_t)(kt + 1) * 128 * NDK;
            float* kdst = Ks + (size_t)(cur ^ 1) * 128 * KS_STRIDE;
            #pragma unroll
            for (int i = 0; i < 8; i++) {
                int s = tid + i * 256;
                int r = s >> 4, c4 = (s & 15) << 2;
                int c = r & 7;
                int srow = (r & ~7) | ((c >> 1) + ((c & 1) << 2));
                cp_a16(&kdst[(size_t)r * KS_STRIDE + c4], ksrc + (size_t)srow * NDK + c4);
            }
            asm volatile("cp.async.commit_group;\n");
            asm volatile("cp.async.wait_group 2;\n");   // drain K(kt) [and Q]
        } else {
            asm volatile("cp.async.wait_group 1;\n");   // drain K(kt)
        }
        __syncthreads();

        if (kt == 0) {
            // Q is prerounded: plain bitcast loads, no cvt.
            #pragma unroll
            for (int ks = 0; ks < 8; ks++) {
                qreg[ks][0] = __float_as_uint(Qs[(size_t)(wm + g    ) * QS_STRIDE + ks * 8 + t    ]);
                qreg[ks][1] = __float_as_uint(Qs[(size_t)(wm + g + 8) * QS_STRIDE + ks * 8 + t    ]);
                qreg[ks][2] = __float_as_uint(Qs[(size_t)(wm + g    ) * QS_STRIDE + ks * 8 + t + 4]);
                qreg[ks][3] = __float_as_uint(Qs[(size_t)(wm + g + 8) * QS_STRIDE + ks * 8 + t + 4]);
            }
        }

        const float* Ksb = Ks + (size_t)cur * 128 * KS_STRIDE;

        // ---- S = Q K^T : warp tile m16 x n128(slots), k=64 ----
        float sacc[16][4];
        #pragma unroll
        for (int i = 0; i < 16; i++)
            #pragma unroll
            for (int j = 0; j < 4; j++) sacc[i][j] = 0.f;

        #pragma unroll
        for (int ks = 0; ks < 8; ks++) {
            #pragma unroll
            for (int ni = 0; ni < 16; ni++) {
                unsigned bb[2];
                int n = ni * 8 + g;
                bb[0] = __float_as_uint(Ksb[(size_t)n * KS_STRIDE + ks * 8 + t    ]);
                bb[1] = __float_as_uint(Ksb[(size_t)n * KS_STRIDE + ks * 8 + t + 4]);
                mma_m16n8k8(sacc[ni], qreg[ks], bb);
            }
        }

        // ---- scale + relpos (per-KEY columns), tile row-max ----
        float m0 = -INFINITY, m1 = -INFINITY;
        const float* rp0 = rp + (size_t)(wm + g    ) * NS + kt * 128 + t;
        const float* rp1 = rp + (size_t)(wm + g + 8) * NS + kt * 128 + t;
        #pragma unroll
        for (int ni = 0; ni < 16; ni++) {
            sacc[ni][0] = sacc[ni][0] * ATTN_SCALE + rp0[ni * 8    ];
            sacc[ni][1] = sacc[ni][1] * ATTN_SCALE + rp0[ni * 8 + 4];
            sacc[ni][2] = sacc[ni][2] * ATTN_SCALE + rp1[ni * 8    ];
            sacc[ni][3] = sacc[ni][3] * ATTN_SCALE + rp1[ni * 8 + 4];
            m0 = fmaxf(m0, fmaxf(sacc[ni][0], sacc[ni][1]));
            m1 = fmaxf(m1, fmaxf(sacc[ni][2], sacc[ni][3]));
        }
        m0 = fmaxf(m0, __shfl_xor_sync(0xFFFFFFFFu, m0, 1));
        m0 = fmaxf(m0, __shfl_xor_sync(0xFFFFFFFFu, m0, 2));
        m1 = fmaxf(m1, __shfl_xor_sync(0xFFFFFFFFu, m1, 1));
        m1 = fmaxf(m1, __shfl_xor_sync(0xFFFFFFFFu, m1, 2));

        float nm0 = fmaxf(rm0, m0), nm1 = fmaxf(rm1, m1);
        float al0 = __expf(rm0 - nm0), al1 = __expf(rm1 - nm1);
        rm0 = nm0; rm1 = nm1;

        // ---- P = exp(S - m) in registers, row sums ----
        float ps0 = 0.f, ps1 = 0.f;
        #pragma unroll
        for (int ni = 0; ni < 16; ni++) {
            sacc[ni][0] = __expf(sacc[ni][0] - nm0);
            sacc[ni][1] = __expf(sacc[ni][1] - nm0);
            sacc[ni][2] = __expf(sacc[ni][2] - nm1);
            sacc[ni][3] = __expf(sacc[ni][3] - nm1);
            ps0 += sacc[ni][0] + sacc[ni][1];
            ps1 += sacc[ni][2] + sacc[ni][3];
        }
        ps0 += __shfl_xor_sync(0xFFFFFFFFu, ps0, 1);
        ps0 += __shfl_xor_sync(0xFFFFFFFFu, ps0, 2);
        ps1 += __shfl_xor_sync(0xFFFFFFFFu, ps1, 1);
        ps1 += __shfl_xor_sync(0xFFFFFFFFu, ps1, 2);
        rs0 = rs0 * al0 + ps0;
        rs1 = rs1 * al1 + ps1;

        // rescale O accumulator
        #pragma unroll
        for (int ni = 0; ni < 8; ni++) {
            oacc[ni][0] *= al0; oacc[ni][1] *= al0;
            oacc[ni][2] *= al1; oacc[ni][3] *= al1;
        }

        // ---- V(kt) visible; K(kt+1) may continue in flight ----
        if (kt + 1 < NS / 128) {
            asm volatile("cp.async.wait_group 1;\n");
        } else {
            asm volatile("cp.async.wait_group 0;\n");
        }
        __syncthreads();

        // ---- O += P V : P A-fragments straight from sacc (permuted match) ----
        #pragma unroll
        for (int ni = 0; ni < 16; ni++) {          // key-block = k-block
            unsigned aP[4];
            aP[0] = f2tf_u(sacc[ni][0]);   // (row g,   k=t)
            aP[1] = f2tf_u(sacc[ni][2]);   // (row g+8, k=t)
            aP[2] = f2tf_u(sacc[ni][1]);   // (row g,   k=t+4)
            aP[3] = f2tf_u(sacc[ni][3]);   // (row g+8, k=t+4)
            #pragma unroll
            for (int nj = 0; nj < 8; nj++) {
                unsigned bb[2];
                int n = nj * 8 + g;
                bb[0] = __float_as_uint(Vs[(size_t)(ni * 8 + t    ) * VS_STRIDE + n]);
                bb[1] = __float_as_uint(Vs[(size_t)(ni * 8 + t + 4) * VS_STRIDE + n]);
                mma_m16n8k8(oacc[nj], aP, bb);
            }
        }
        __syncthreads();   // all warps done with Vs / Ks[cur] before next-iter writes
    }

    // ---- epilogue: normalize, write ctx combined-head ----
    float inv0 = 1.f / rs0, inv1 = 1.f / rs1;
    #pragma unroll
    for (int ni = 0; ni < 8; ni++) {
        int d = ni * 8 + 2 * t;
        size_t i0 = ((size_t)b * NS + qt * 128 + wm + g    ) * NDM + h * 64 + d;
        size_t i1 = ((size_t)b * NS + qt * 128 + wm + g + 8) * NDM + h * 64 + d;
        *(float2*)(g_ctx + i0) = make_float2(oacc[ni][0] * inv0, oacc[ni][1] * inv0);
        *(float2*)(g_ctx + i1) = make_float2(oacc[ni][2] * inv1, oacc[ni][3] * inv1);
    }
}

// ---------------------------------------------------------------------------
// Kernel 3: out = ctx @ Wo^T + bo (round-7 measured configuration).
// ---------------------------------------------------------------------------
__global__ __launch_bounds__(256) void out_proj_kernel(
    const float* __restrict__ Wo, const float* __restrict__ bo, float* __restrict__ out)
{
    extern __shared__ float smg[];
    float acc[4][4][4];
    #pragma unroll
    for (int i = 0; i < 4; i++)
        #pragma unroll
        for (int j = 0; j < 4; j++)
            #pragma unroll
            for (int k = 0; k < 4; k++) acc[i][j][k] = 0.f;

    gemm_tn_128x128_db(g_ctx + (size_t)blockIdx.y * 128 * NDM,
                       Wo    + (size_t)blockIdx.x * 128 * NDM, NDM, smg, acc);

    const int tid = threadIdx.x, lane = tid & 31, warp = tid >> 5;
    const int g = lane >> 2, t = lane & 3;
    const int wm0 = (warp & 1) * 64, wn0 = (warp >> 1) * 32;
    const int row0 = blockIdx.y * 128, col0 = blockIdx.x * 128;

    #pragma unroll
    for (int mi = 0; mi < 4; mi++) {
        #pragma unroll
        for (int ni = 0; ni < 4; ni++) {
            int n = col0 + wn0 + ni * 8 + 2 * t;
            float b0v = bo[n], b1v = bo[n + 1];
            #pragma unroll
            for (int half = 0; half < 2; half++) {
                int m = row0 + wm0 + mi * 16 + g + half * 8;
                *(float2*)(out + (size_t)m * NDM + n) =
                    make_float2(acc[mi][ni][half * 2 + 0] + b0v,
                                acc[mi][ni][half * 2 + 1] + b1v);
            }
        }
    }
}

// ---------------------------------------------------------------------------
// Launch
// ---------------------------------------------------------------------------
extern "C" void kernel_launch(void* const* d_in, const int* in_sizes, int n_in,
                              void* d_out, int out_size)
{
    (void)in_sizes; (void)n_in; (void)out_size;
    const float* Q      = (const float*)d_in[0];
    const float* K      = (const float*)d_in[1];
    const float* V      = (const float*)d_in[2];
    const float* Wq     = (const float*)d_in[3];
    const float* bq     = (const float*)d_in[4];
    const float* Wk     = (const float*)d_in[5];
    const float* bk     = (const float*)d_in[6];
    const float* Wv     = (const float*)d_in[7];
    const float* bv     = (const float*)d_in[8];
    const float* Wo     = (const float*)d_in[9];
    const float* bo     = (const float*)d_in[10];
    const float* relpos = (const float*)d_in[11];
    float* out = (float*)d_out;

    cudaFuncSetAttribute(flash_attn_kernel,
                         cudaFuncAttributeMaxDynamicSharedMemorySize, ATTN_SMEM_BYTES);
    cudaFuncSetAttribute(qkv_proj_kernel,
                         cudaFuncAttributeMaxDynamicSharedMemorySize, GEMM_SMEM_BYTES);
    cudaFuncSetAttribute(out_proj_kernel,
                         cudaFuncAttributeMaxDynamicSharedMemorySize, GEMM_SMEM_BYTES);

    dim3 blk(256);
    // 1) q,k,v = proj(Q/K/V), head-split, TF32-prerounded
    qkv_proj_kernel<<<dim3(NDM / 128, NT / 128, 3), blk, GEMM_SMEM_BYTES>>>(
        Q, K, V, Wq, Wk, Wv, bq, bk, bv);
    // 2) fused attention (scores + relpos + softmax + ctx), batch-major grid for L2 relpos reuse
    flash_attn_kernel<<<dim3(NB, NS / 128, NH), blk, ATTN_SMEM_BYTES>>>(relpos);
    // 3) out = ctx @ Wo^T + bo
    out_proj_kernel<<<dim3(NDM / 128, NT / 128, 1), blk, GEMM_SMEM_BYTES>>>(Wo, bo, out);
}